// round 13
// baseline (speedup 1.0000x reference)
#include <cuda_runtime.h>
#include <cuda_bf16.h>
#include <cstdint>
#include <stdint.h>
#include <math.h>

#define BB 4
#define CC 256
#define MID 64
#define HWN 4096
#define EPSV 1e-5f
#define KC 32
#define SB 40      // smem row stride in bf16 (80B; ldmatrix conflict-free)

// ---------------- scratch (device globals; no allocation allowed) ----------
__device__ __nv_bfloat16 g_Whi[192 * CC];
__device__ __nv_bfloat16 g_Wlo[192 * CC];
__device__ float g_bcat[192];
__device__ __nv_bfloat16 g_Xhi[(size_t)BB * HWN * CC];  // x^T bf16 hi: [b][n][c]
__device__ __nv_bfloat16 g_Xlo[(size_t)BB * HWN * CC];
__device__ __nv_bfloat16 g_FGHkhi[(size_t)BB * 192 * HWN]; // FGH bf16 hi: [b][r][n]
__device__ __nv_bfloat16 g_FGHklo[(size_t)BB * 192 * HWN]; // FGH bf16 lo
__device__ __nv_bfloat16 g_Fthi[(size_t)BB * HWN * MID]; // F^T: [b][n][k]
__device__ __nv_bfloat16 g_Ftlo[(size_t)BB * HWN * MID];
__device__ float g_gv[BB * MID];
__device__ float g_gram[3 * BB * MID * MID]; // p0: F F^T, p1: G F^T, p2: G H^T
__device__ float g_s[BB];
__device__ int g_cntA[BB];   // gram p0/p1 completion (target 32)
__device__ int g_cntB[BB];   // gv completion (target 16)

// ---------------- PTX helpers ----------------
__device__ __forceinline__ uint32_t s2u(const void* p) {
    uint32_t a;
    asm("{ .reg .u64 t; cvta.to.shared.u64 t, %1; cvt.u32.u64 %0, t; }" : "=r"(a) : "l"(p));
    return a;
}

__device__ __forceinline__ void mma16816(float& c0, float& c1, float& c2, float& c3,
                                         uint32_t a0, uint32_t a1, uint32_t a2, uint32_t a3,
                                         uint32_t b0, uint32_t b1) {
    asm volatile(
        "mma.sync.aligned.m16n8k16.row.col.f32.bf16.bf16.f32 "
        "{%0,%1,%2,%3}, {%4,%5,%6,%7}, {%8,%9}, {%0,%1,%2,%3};"
        : "+f"(c0), "+f"(c1), "+f"(c2), "+f"(c3)
        : "r"(a0), "r"(a1), "r"(a2), "r"(a3), "r"(b0), "r"(b1));
}

#define LDSM4(r0, r1, r2, r3, addr) \
    asm volatile("ldmatrix.sync.aligned.m8n8.x4.shared.b16 {%0,%1,%2,%3}, [%4];" \
                 : "=r"(r0), "=r"(r1), "=r"(r2), "=r"(r3) : "r"(addr))

__device__ __forceinline__ uint32_t packbf(float f0, float f1) {
    __nv_bfloat162 h = __floats2bfloat162_rn(f0, f1);
    return *(uint32_t*)&h;
}

// 8 mma block: acc[2][4][4] += A(2 frags) x B(4 frags)
#define MMA_BLOCK(acc, a0, a1, b0, b1) do {                                   \
    mma16816(acc[0][0][0], acc[0][0][1], acc[0][0][2], acc[0][0][3],          \
             a0[0], a0[1], a0[2], a0[3], b0[0], b0[1]);                       \
    mma16816(acc[0][1][0], acc[0][1][1], acc[0][1][2], acc[0][1][3],          \
             a0[0], a0[1], a0[2], a0[3], b0[2], b0[3]);                       \
    mma16816(acc[0][2][0], acc[0][2][1], acc[0][2][2], acc[0][2][3],          \
             a0[0], a0[1], a0[2], a0[3], b1[0], b1[1]);                       \
    mma16816(acc[0][3][0], acc[0][3][1], acc[0][3][2], acc[0][3][3],          \
             a0[0], a0[1], a0[2], a0[3], b1[2], b1[3]);                       \
    mma16816(acc[1][0][0], acc[1][0][1], acc[1][0][2], acc[1][0][3],          \
             a1[0], a1[1], a1[2], a1[3], b0[0], b0[1]);                       \
    mma16816(acc[1][1][0], acc[1][1][1], acc[1][1][2], acc[1][1][3],          \
             a1[0], a1[1], a1[2], a1[3], b0[2], b0[3]);                       \
    mma16816(acc[1][2][0], acc[1][2][1], acc[1][2][2], acc[1][2][3],          \
             a1[0], a1[1], a1[2], a1[3], b1[0], b1[1]);                       \
    mma16816(acc[1][3][0], acc[1][3][1], acc[1][3][2], acc[1][3][3],          \
             a1[0], a1[1], a1[2], a1[3], b1[2], b1[3]);                       \
} while (0)

// Dedup'd 3-pass inner step: load 8 unique LDSM4, run 3 MMA blocks.
#define SPLIT3_STEP(acc, uAhi, uAlo, uBhi, uBlo, aoff, boff, kof) do {        \
    uint32_t ah0[4], ah1[4], al0[4], al1[4];                                  \
    uint32_t bh0[4], bh1[4], bl0[4], bl1[4];                                  \
    LDSM4(ah0[0], ah0[1], ah0[2], ah0[3], (uAhi) + (aoff) + (kof));           \
    LDSM4(ah1[0], ah1[1], ah1[2], ah1[3], (uAhi) + (aoff) + 16 * SB * 2 + (kof)); \
    LDSM4(bh0[0], bh0[1], bh0[2], bh0[3], (uBhi) + (boff) + (kof));           \
    LDSM4(bh1[0], bh1[1], bh1[2], bh1[3], (uBhi) + (boff) + 16 * SB * 2 + (kof)); \
    LDSM4(al0[0], al0[1], al0[2], al0[3], (uAlo) + (aoff) + (kof));           \
    LDSM4(al1[0], al1[1], al1[2], al1[3], (uAlo) + (aoff) + 16 * SB * 2 + (kof)); \
    LDSM4(bl0[0], bl0[1], bl0[2], bl0[3], (uBlo) + (boff) + (kof));           \
    LDSM4(bl1[0], bl1[1], bl1[2], bl1[3], (uBlo) + (boff) + 16 * SB * 2 + (kof)); \
    MMA_BLOCK(acc, ah0, ah1, bh0, bh1);                                       \
    MMA_BLOCK(acc, al0, al1, bh0, bh1);                                       \
    MMA_BLOCK(acc, ah0, ah1, bl0, bl1);                                       \
} while (0)

// ---------------- reductions ----------------
__device__ __forceinline__ float warpSum(float v) {
#pragma unroll
    for (int o = 16; o > 0; o >>= 1) v += __shfl_xor_sync(0xffffffffu, v, o);
    return v;
}

// ---------------- kernel 1: prep (BN fold + weight split) + xsplit fused ----
__global__ __launch_bounds__(256) void k_prepx(
        const float* __restrict__ x,
        const float* __restrict__ Wf, const float* __restrict__ bf,
        const float* __restrict__ gaf, const float* __restrict__ bef,
        const float* __restrict__ mef, const float* __restrict__ vaf,
        const float* __restrict__ Wg, const float* __restrict__ bg,
        const float* __restrict__ gag, const float* __restrict__ beg,
        const float* __restrict__ meg, const float* __restrict__ vag,
        const float* __restrict__ Wh, const float* __restrict__ bh) {
    int bid = blockIdx.x;
    int tid = threadIdx.x;
    if (bid >= 1024) {
        int idx = (bid - 1024) * 256 + tid;   // < 49152
        g_gram[idx] = 0.f;
        if (idx < BB) { g_cntA[idx] = 0; g_cntB[idx] = 0; }
        int o = idx / CC, c = idx % CC;
        float w, bias;
        if (o < 64) {
            float inv = gaf[o] * rsqrtf(vaf[o] + EPSV);
            w = Wf[o * CC + c] * inv;
            bias = bf[o] * inv + bef[o] - mef[o] * inv;
        } else if (o < 128) {
            int oo = o - 64;
            float inv = gag[oo] * rsqrtf(vag[oo] + EPSV);
            w = Wg[oo * CC + c] * inv;
            bias = bg[oo] * inv + beg[oo] - meg[oo] * inv;
        } else {
            int oo = o - 128;
            w = Wh[oo * CC + c];
            bias = bh[oo];
        }
        __nv_bfloat16 hi = __float2bfloat16(w);
        __nv_bfloat16 lo = __float2bfloat16(w - __bfloat162float(hi));
        g_Whi[idx] = hi;
        g_Wlo[idx] = lo;
        if (c == 0) g_bcat[o] = bias;
        return;
    }
    __shared__ float ts[64][65];  // [n][c]
    int b = bid >> 8;
    int ct = ((bid >> 6) & 3) * 64, nt = (bid & 63) * 64;
    const float* xb = x + (size_t)b * CC * HWN;
#pragma unroll
    for (int i = 0; i < 4; i++) {
        int idx = i * 256 + tid;
        int c = idx >> 4, q = idx & 15;
        float4 v = *(const float4*)(xb + (size_t)(ct + c) * HWN + nt + q * 4);
        ts[q * 4 + 0][c] = v.x; ts[q * 4 + 1][c] = v.y;
        ts[q * 4 + 2][c] = v.z; ts[q * 4 + 3][c] = v.w;
    }
    __syncthreads();
#pragma unroll
    for (int i = 0; i < 8; i++) {
        int pidx = i * 256 + tid;
        int n = pidx >> 5, j = pidx & 31;
        float f0 = ts[n][2 * j], f1 = ts[n][2 * j + 1];
        __nv_bfloat16 h0 = __float2bfloat16(f0), h1 = __float2bfloat16(f1);
        float l0 = f0 - __bfloat162float(h0), l1 = f1 - __bfloat162float(h1);
        size_t o = ((size_t)b * HWN + nt + n) * CC + ct + 2 * j;
        __nv_bfloat162 hp; hp.x = h0; hp.y = h1;
        *(uint32_t*)(g_Xhi + o) = *(uint32_t*)&hp;
        *(uint32_t*)(g_Xlo + o) = packbf(l0, l1);
    }
}

// ---------------- kernel 2: FGH via mma.sync (dedup'd split passes) ---------
__global__ __launch_bounds__(256) void k_fgh_mma() {
    __shared__ __align__(16) char sbuf[33024];
    __nv_bfloat16* sp = (__nv_bfloat16*)sbuf;
    __nv_bfloat16* sWhi = sp;
    __nv_bfloat16* sWlo = sWhi + 64 * SB;
    __nv_bfloat16* sXhi = sWlo + 64 * SB;
    __nv_bfloat16* sXlo = sXhi + 128 * SB;
    float* fs = (float*)sbuf;                 // epilogue staging [64][129]

    int tid = threadIdx.x;
    int wid = tid >> 5, lane = tid & 31;
    int b = blockIdx.z, mt = blockIdx.y;
    int nbase = blockIdx.x * 128;
    int wm = wid & 1, wn = wid >> 1;

    uint32_t ub = s2u(sbuf);
    uint32_t uWhi = ub, uWlo = ub + 64 * SB * 2;
    uint32_t uXhi = uWlo + 64 * SB * 2, uXlo = uXhi + 128 * SB * 2;

    const __nv_bfloat16* Xh = g_Xhi + (size_t)b * HWN * CC;
    const __nv_bfloat16* Xl = g_Xlo + (size_t)b * HWN * CC;

    float acc[2][4][4];
#pragma unroll
    for (int i = 0; i < 2; i++)
#pragma unroll
        for (int j = 0; j < 4; j++)
#pragma unroll
            for (int q = 0; q < 4; q++) acc[i][j][q] = 0.f;

    uint32_t aoff = ((uint32_t)(wm * 32 + (lane & 15)) * SB + (lane >> 4) * 8) * 2;
    uint32_t boff = ((uint32_t)(wn * 32 + ((lane >> 4) & 1) * 8 + (lane & 7)) * SB
                     + ((lane >> 3) & 1) * 8) * 2;

    int arow = tid >> 2, auc = tid & 3;
    const __nv_bfloat16* srcW0 = g_Whi + (size_t)(mt * 64 + arow) * CC + auc * 8;
    const __nv_bfloat16* srcW1 = g_Wlo + (size_t)(mt * 64 + arow) * CC + auc * 8;
    const __nv_bfloat16* srcX0 = Xh + (size_t)(nbase + arow) * CC + auc * 8;
    const __nv_bfloat16* srcX1 = Xh + (size_t)(nbase + arow + 64) * CC + auc * 8;
    const __nv_bfloat16* srcX2 = Xl + (size_t)(nbase + arow) * CC + auc * 8;
    const __nv_bfloat16* srcX3 = Xl + (size_t)(nbase + arow + 64) * CC + auc * 8;

    uint4 pW0 = *(const uint4*)(srcW0);
    uint4 pW1 = *(const uint4*)(srcW1);
    uint4 pX0 = *(const uint4*)(srcX0);
    uint4 pX1 = *(const uint4*)(srcX1);
    uint4 pX2 = *(const uint4*)(srcX2);
    uint4 pX3 = *(const uint4*)(srcX3);

#pragma unroll 1
    for (int ki = 0; ki < CC / KC; ki++) {
        *(uint4*)(sWhi + arow * SB + auc * 8) = pW0;
        *(uint4*)(sWlo + arow * SB + auc * 8) = pW1;
        *(uint4*)(sXhi + arow * SB + auc * 8) = pX0;
        *(uint4*)(sXhi + (arow + 64) * SB + auc * 8) = pX1;
        *(uint4*)(sXlo + arow * SB + auc * 8) = pX2;
        *(uint4*)(sXlo + (arow + 64) * SB + auc * 8) = pX3;
        __syncthreads();
        if (ki < CC / KC - 1) {
            int kt = (ki + 1) * KC;
            pW0 = *(const uint4*)(srcW0 + kt);
            pW1 = *(const uint4*)(srcW1 + kt);
            pX0 = *(const uint4*)(srcX0 + kt);
            pX1 = *(const uint4*)(srcX1 + kt);
            pX2 = *(const uint4*)(srcX2 + kt);
            pX3 = *(const uint4*)(srcX3 + kt);
        }
#pragma unroll
        for (int ks = 0; ks < 2; ks++) {
            uint32_t kof = ks * 32;
            SPLIT3_STEP(acc, uWhi, uWlo, uXhi, uXlo, aoff, boff, kof);
        }
        __syncthreads();
    }

    int rq = lane >> 2;
    int cq = (lane & 3) * 2;
#pragma unroll
    for (int mf = 0; mf < 2; mf++) {
#pragma unroll
        for (int half = 0; half < 2; half++) {
            int orow = mt * 64 + wm * 32 + mf * 16 + rq + half * 8;
            float bias = g_bcat[orow];
            bool rl = (orow < 128);
            size_t base = ((size_t)b * 192 + orow) * HWN + nbase + wn * 32;
#pragma unroll
            for (int nf = 0; nf < 4; nf++) {
                float v0 = acc[mf][nf][half * 2 + 0] + bias;
                float v1 = acc[mf][nf][half * 2 + 1] + bias;
                if (rl) { v0 = fmaxf(v0, 0.f); v1 = fmaxf(v1, 0.f); }
                __nv_bfloat16 h0 = __float2bfloat16(v0), h1 = __float2bfloat16(v1);
                float l0 = v0 - __bfloat162float(h0), l1 = v1 - __bfloat162float(h1);
                __nv_bfloat162 hp; hp.x = h0; hp.y = h1;
                *(uint32_t*)(g_FGHkhi + base + nf * 8 + cq) = *(uint32_t*)&hp;
                *(uint32_t*)(g_FGHklo + base + nf * 8 + cq) = packbf(l0, l1);
            }
        }
    }

    // mt==0: emit F^T bf16 hi/lo (holds all 64 F rows)
    if (mt == 0) {
        __syncthreads();
#pragma unroll
        for (int mf = 0; mf < 2; mf++)
#pragma unroll
            for (int half = 0; half < 2; half++) {
                int k = wm * 32 + mf * 16 + rq + half * 8;
                float bias = g_bcat[k];
#pragma unroll
                for (int nf = 0; nf < 4; nf++) {
                    int n = wn * 32 + nf * 8 + cq;
                    fs[k * 129 + n] = fmaxf(acc[mf][nf][half * 2 + 0] + bias, 0.f);
                    fs[k * 129 + n + 1] = fmaxf(acc[mf][nf][half * 2 + 1] + bias, 0.f);
                }
            }
        __syncthreads();
#pragma unroll
        for (int i = 0; i < 16; i++) {
            int pidx = i * 256 + tid;
            int n = pidx >> 5, j = pidx & 31;
            float f0 = fs[(2 * j) * 129 + n], f1 = fs[(2 * j + 1) * 129 + n];
            __nv_bfloat16 h0 = __float2bfloat16(f0), h1 = __float2bfloat16(f1);
            float l0 = f0 - __bfloat162float(h0), l1 = f1 - __bfloat162float(h1);
            size_t o = ((size_t)b * HWN + nbase + n) * MID + 2 * j;
            __nv_bfloat162 hp; hp.x = h0; hp.y = h1;
            *(uint32_t*)(g_Fthi + o) = *(uint32_t*)&hp;
            *(uint32_t*)(g_Ftlo + o) = packbf(l0, l1);
        }
    }
}

// ---------------- kernel 3: Gram + gv + s (device-side completion) ----------
// grid (BB, 4, 16), 128 thr.
//  p<3: gram p over 8 n-chunks of 32 (atomics); p<2 blocks bump g_cntA[b].
//  p==3: gv for k=z*4+wid; bump g_cntB[b]; block z==15 then spins for
//        cntA==32 && cntB==16 and computes s.
__global__ __launch_bounds__(128) void k_gramgv(const float* __restrict__ v0) {
    __shared__ __align__(16) __nv_bfloat16 sg[4 * 64 * SB];
    __shared__ float gvs[64], fvs[64], gvvs[64];
    int tid = threadIdx.x;
    int wid = tid >> 5, lane = tid & 31;
    int b = blockIdx.x, p = blockIdx.y, z = blockIdx.z;

    if (p == 3) {
        int k = z * 4 + wid;
        const __nv_bfloat16* rh = g_FGHkhi + ((size_t)b * 192 + 64 + k) * HWN;
        const __nv_bfloat16* rl = g_FGHklo + ((size_t)b * 192 + 64 + k) * HWN;
        const float* v = v0 + (size_t)b * HWN;
        float s = 0.f;
#pragma unroll 4
        for (int it = 0; it < 16; it++) {
            int n0 = (it * 32 + lane) * 8;
            uint4 hu = *(const uint4*)(rh + n0);
            uint4 lu = *(const uint4*)(rl + n0);
            float4 va = *(const float4*)(v + n0);
            float4 vb = *(const float4*)(v + n0 + 4);
            uint32_t hw[4] = {hu.x, hu.y, hu.z, hu.w};
            uint32_t lw[4] = {lu.x, lu.y, lu.z, lu.w};
            float vv[8] = {va.x, va.y, va.z, va.w, vb.x, vb.y, vb.z, vb.w};
#pragma unroll
            for (int j = 0; j < 4; j++) {
                float2 hf = __bfloat1622float2(*(__nv_bfloat162*)&hw[j]);
                float2 lf = __bfloat1622float2(*(__nv_bfloat162*)&lw[j]);
                s += (hf.x + lf.x) * vv[2 * j] + (hf.y + lf.y) * vv[2 * j + 1];
            }
        }
        s = warpSum(s);
        if (lane == 0) g_gv[b * MID + k] = s;
        __threadfence();
        __syncthreads();
        if (tid == 0) atomicAdd(&g_cntB[b], 1);
        if (z != 15) return;

        // ---- spinner: wait for grams p0/p1 (32 blocks) + gv (16 blocks) ----
        if (tid == 0) {
            while (atomicAdd(&g_cntA[b], 0) < 32 || atomicAdd(&g_cntB[b], 0) < 16) {}
        }
        __syncthreads();
        __threadfence();
        if (tid < 64) gvs[tid] = __ldcg(&g_gv[b * MID + tid]);
        __syncthreads();
        {
            int row = tid;                    // 0..127
            int pm = (row < 64) ? 0 : 1;
            int rl2 = row & 63;
            const float* A = g_gram + ((size_t)pm * BB + b) * MID * MID + rl2 * MID;
            float ps = 0.f;
#pragma unroll
            for (int j = 0; j < 64; j++) ps += __ldcg(A + j) * gvs[j];
            if (row < 64) fvs[rl2] = ps; else gvvs[rl2] = ps;
        }
        __syncthreads();
        if (tid < 32) {
            float ss = fvs[tid] * gvs[tid] + fvs[tid + 32] * gvs[tid + 32];
            float num = fvs[tid] * gvvs[tid] + fvs[tid + 32] * gvvs[tid + 32];
            ss = warpSum(ss);
            num = warpSum(num);
            if (tid == 0) g_s[b] = num / ss;
        }
        return;
    }

    __nv_bfloat16* sAhi = sg;
    __nv_bfloat16* sAlo = sAhi + 64 * SB;
    __nv_bfloat16* sBhi = sAlo + 64 * SB;
    __nv_bfloat16* sBlo = sBhi + 64 * SB;
    uint32_t ub = s2u(sg);
    uint32_t uAhi = ub, uAlo = ub + 64 * SB * 2;
    uint32_t uBhi = uAlo + 64 * SB * 2, uBlo = uBhi + 64 * SB * 2;

    int aroff = (p == 0) ? 0 : 64;
    int broff = (p == 2) ? 128 : 0;
    int wi = wid & 1, wj = wid >> 1;

    float acc[2][4][4];
#pragma unroll
    for (int i = 0; i < 2; i++)
#pragma unroll
        for (int j = 0; j < 4; j++)
#pragma unroll
            for (int q = 0; q < 4; q++) acc[i][j][q] = 0.f;

    uint32_t aoff = ((uint32_t)(wi * 32 + (lane & 15)) * SB + (lane >> 4) * 8) * 2;
    uint32_t boff = ((uint32_t)(wj * 32 + ((lane >> 4) & 1) * 8 + (lane & 7)) * SB
                     + ((lane >> 3) & 1) * 8) * 2;

#pragma unroll 1
    for (int l = 0; l < 8; l++) {
        int nb = z * 256 + l * 32;
#pragma unroll
        for (int i = 0; i < 2; i++) {
            int unit = i * 128 + tid;      // 256 units = 64 rows x 4 uint4
            int row = unit >> 2, uc = unit & 3;
            size_t ga = ((size_t)b * 192 + aroff + row) * HWN + nb + uc * 8;
            size_t gb = ((size_t)b * 192 + broff + row) * HWN + nb + uc * 8;
            *(uint4*)(sAhi + row * SB + uc * 8) = *(const uint4*)(g_FGHkhi + ga);
            *(uint4*)(sAlo + row * SB + uc * 8) = *(const uint4*)(g_FGHklo + ga);
            *(uint4*)(sBhi + row * SB + uc * 8) = *(const uint4*)(g_FGHkhi + gb);
            *(uint4*)(sBlo + row * SB + uc * 8) = *(const uint4*)(g_FGHklo + gb);
        }
        __syncthreads();
#pragma unroll
        for (int ks = 0; ks < 2; ks++) {
            uint32_t kof = ks * 32;
            SPLIT3_STEP(acc, uAhi, uAlo, uBhi, uBlo, aoff, boff, kof);
        }
        __syncthreads();
    }

    float* dst = g_gram + ((size_t)p * BB + b) * MID * MID;
    int rq = lane >> 2, cq = (lane & 3) * 2;
#pragma unroll
    for (int mf = 0; mf < 2; mf++)
#pragma unroll
        for (int half = 0; half < 2; half++) {
            int i = wi * 32 + mf * 16 + rq + half * 8;
#pragma unroll
            for (int nf = 0; nf < 4; nf++) {
                int j = wj * 32 + nf * 8 + cq;
                atomicAdd(&dst[i * MID + j], acc[mf][nf][half * 2 + 0]);
                atomicAdd(&dst[i * MID + j + 1], acc[mf][nf][half * 2 + 1]);
            }
        }
    if (p < 2) {
        __threadfence();
        __syncthreads();
        if (tid == 0) atomicAdd(&g_cntA[b], 1);
    }
}

// ---------------- kernel 4: out = (1/s)(Wv M^T) @ F + bv + x ----------------
// Prologue computes this CTA's 64x64 Q tile (Q = Wv M^T, unscaled) in smem;
// main loop identical dedup'd 3-pass mma; epilogue applies 1/s + bias + x.
__global__ __launch_bounds__(256) void k_out_mma(const float* __restrict__ x,
                                                 const float* __restrict__ Wv,
                                                 const float* __restrict__ bv,
                                                 float* __restrict__ out) {
    __shared__ __align__(16) char sbuf[47360];
    __nv_bfloat16* sp = (__nv_bfloat16*)sbuf;
    __nv_bfloat16* sAhi = sp;
    __nv_bfloat16* sAlo = sAhi + 64 * SB;
    __nv_bfloat16* sBhi = sAlo + 64 * SB;
    __nv_bfloat16* sBlo = sBhi + 128 * SB;
    float* Qs = (float*)(sbuf + 30720);      // [64][65] fp32 Q tile

    int tid = threadIdx.x;
    int wid = tid >> 5, lane = tid & 31;
    int b = blockIdx.z, mt = blockIdx.y;
    int nbase = blockIdx.x * 128;
    int wm = wid & 1, wn = wid >> 1;

    // ---- prologue: Q[o][k] = sum_c Wv[mt*64+o][c] * M[k][c] ----
    {
        float* Wvs = (float*)sbuf;            // [64][65]
        float* Ms = (float*)(sbuf + 16640);   // [64][65]
        const float* Mb = g_gram + ((size_t)2 * BB + b) * MID * MID;
#pragma unroll
        for (int i = 0; i < 16; i++) {
            int idx = i * 256 + tid;          // [0,4096)
            int r = idx >> 6, c = idx & 63;
            Wvs[r * 65 + c] = Wv[(size_t)(mt * 64 + r) * MID + c];
            Ms[r * 65 + c] = Mb[idx];
        }
        __syncthreads();
        int to = tid >> 4, tk = tid & 15;     // 16x16 thread grid, 4x4 tile each
        float q[4][4] = {};
#pragma unroll
        for (int c = 0; c < 64; c++) {
            float wv[4], mm[4];
#pragma unroll
            for (int i = 0; i < 4; i++) wv[i] = Wvs[(to * 4 + i) * 65 + c];
#pragma unroll
            for (int j = 0; j < 4; j++) mm[j] = Ms[(tk * 4 + j) * 65 + c];
#pragma unroll
            for (int i = 0; i < 4; i++)
#pragma unroll
                for (int j = 0; j < 4; j++) q[i][j] += wv[i] * mm[j];
        }
        __syncthreads();
#pragma unroll
        for (int i = 0; i < 4; i++)
#pragma unroll
            for (int j = 0; j < 4; j++)
                Qs[(to * 4 + i) * 65 + tk * 4 + j] = q[i][j];
        __syncthreads();
    }

    uint32_t ub = s2u(sbuf);
    uint32_t uAhi = ub, uAlo = ub + 64 * SB * 2;
    uint32_t uBhi = uAlo + 64 * SB * 2, uBlo = uBhi + 128 * SB * 2;

    float acc[2][4][4];
#pragma unroll
    for (int i = 0; i < 2; i++)
#pragma unroll
        for (int j = 0; j < 4; j++)
#pragma unroll
            for (int q = 0; q < 4; q++) acc[i][j][q] = 0.f;

    uint32_t aoff = ((uint32_t)(wm * 32 + (lane & 15)) * SB + (lane >> 4) * 8) * 2;
    uint32_t boff = ((uint32_t)(wn * 32 + ((lane >> 4) & 1) * 8 + (lane & 7)) * SB
                     + ((lane >> 3) & 1) * 8) * 2;

    int arow = tid >> 2, auc = tid & 3;
#pragma unroll 1
    for (int ki = 0; ki < MID / KC; ki++) {
        int kt = ki * KC;
        // A-fill from Qs (fp32 -> bf16 hi/lo split)
        {
            uint32_t hi4[4], lo4[4];
#pragma unroll
            for (int e = 0; e < 4; e++) {
                float f0 = Qs[arow * 65 + kt + auc * 8 + 2 * e];
                float f1 = Qs[arow * 65 + kt + auc * 8 + 2 * e + 1];
                __nv_bfloat16 h0 = __float2bfloat16(f0), h1 = __float2bfloat16(f1);
                float l0 = f0 - __bfloat162float(h0), l1 = f1 - __bfloat162float(h1);
                __nv_bfloat162 hp; hp.x = h0; hp.y = h1;
                hi4[e] = *(uint32_t*)&hp;
                lo4[e] = packbf(l0, l1);
            }
            *(uint4*)(sAhi + arow * SB + auc * 8) = *(uint4*)hi4;
            *(uint4*)(sAlo + arow * SB + auc * 8) = *(uint4*)lo4;
        }
        // B-fill from global F^T
#pragma unroll
        for (int i = 0; i < 2; i++) {
            int unit = i * 256 + tid;
            int row = unit >> 2, uc = unit & 3;
            *(uint4*)(sBhi + row * SB + uc * 8) =
                *(const uint4*)(g_Fthi + ((size_t)b * HWN + nbase + row) * MID + kt + uc * 8);
            *(uint4*)(sBlo + row * SB + uc * 8) =
                *(const uint4*)(g_Ftlo + ((size_t)b * HWN + nbase + row) * MID + kt + uc * 8);
        }
        __syncthreads();
#pragma unroll
        for (int ks = 0; ks < 2; ks++) {
            uint32_t kof = ks * 32;
            SPLIT3_STEP(acc, uAhi, uAlo, uBhi, uBlo, aoff, boff, kof);
        }
        __syncthreads();
    }

    float inv_s = 1.f / g_s[b];
    int rq = lane >> 2;
    int cq = (lane & 3) * 2;
#pragma unroll
    for (int mf = 0; mf < 2; mf++) {
#pragma unroll
        for (int half = 0; half < 2; half++) {
            int orow = mt * 64 + wm * 32 + mf * 16 + rq + half * 8;
            float bias = bv[orow];
            size_t rowoff = ((size_t)b * CC + orow) * HWN + nbase + wn * 32;
#pragma unroll
            for (int nf = 0; nf < 4; nf++) {
                size_t off = rowoff + nf * 8 + cq;
                float2 xr = *(const float2*)(x + off);
                float2 v;
                v.x = acc[mf][nf][half * 2 + 0] * inv_s + bias + xr.x;
                v.y = acc[mf][nf][half * 2 + 1] * inv_s + bias + xr.y;
                *(float2*)(out + off) = v;
            }
        }
    }
}

// ---------------- launch ----------------
extern "C" void kernel_launch(void* const* d_in, const int* in_sizes, int n_in,
                              void* d_out, int out_size) {
    (void)in_sizes; (void)n_in; (void)out_size;
    const float* x   = (const float*)d_in[0];
    const float* Wf  = (const float*)d_in[1];
    const float* bf  = (const float*)d_in[2];
    const float* gaf = (const float*)d_in[3];
    const float* bef = (const float*)d_in[4];
    const float* mef = (const float*)d_in[5];
    const float* vaf = (const float*)d_in[6];
    const float* Wg  = (const float*)d_in[7];
    const float* bg  = (const float*)d_in[8];
    const float* gag = (const float*)d_in[9];
    const float* beg = (const float*)d_in[10];
    const float* meg = (const float*)d_in[11];
    const float* vag = (const float*)d_in[12];
    const float* Wh  = (const float*)d_in[13];
    const float* bh  = (const float*)d_in[14];
    const float* Wv  = (const float*)d_in[15];
    const float* bv  = (const float*)d_in[16];
    const float* v0  = (const float*)d_in[17];
    float* out = (float*)d_out;

    k_prepx<<<1024 + 192, 256>>>(x, Wf, bf, gaf, bef, mef, vaf,
                                 Wg, bg, gag, beg, meg, vag, Wh, bh);
    k_fgh_mma<<<dim3(HWN / 128, 3, BB), 256>>>();
    k_gramgv<<<dim3(BB, 4, 16), 128>>>(v0);
    k_out_mma<<<dim3(HWN / 128, 4, BB), 256>>>(x, Wv, bv, out);
}

// round 14
// speedup vs baseline: 1.0529x; 1.0529x over previous
#include <cuda_runtime.h>
#include <cuda_bf16.h>
#include <cstdint>
#include <stdint.h>
#include <math.h>

#define BB 4
#define CC 256
#define MID 64
#define HWN 4096
#define EPSV 1e-5f
#define KC 32
#define SB 40      // smem row stride in bf16 (80B; ldmatrix conflict-free)

// ---------------- scratch (device globals; no allocation allowed) ----------
__device__ __nv_bfloat16 g_Whi[192 * CC];
__device__ __nv_bfloat16 g_Wlo[192 * CC];
__device__ float g_bcat[192];
__device__ __nv_bfloat16 g_Xhi[(size_t)BB * HWN * CC];  // x^T bf16 hi: [b][n][c]
__device__ __nv_bfloat16 g_Xlo[(size_t)BB * HWN * CC];
__device__ __nv_bfloat16 g_FGHkhi[(size_t)BB * 192 * HWN]; // FGH bf16 hi: [b][r][n]
__device__ __nv_bfloat16 g_FGHklo[(size_t)BB * 192 * HWN]; // FGH bf16 lo
__device__ __nv_bfloat16 g_Fthi[(size_t)BB * HWN * MID]; // F^T: [b][n][k]
__device__ __nv_bfloat16 g_Ftlo[(size_t)BB * HWN * MID];
__device__ float g_gv[BB * MID];
__device__ float g_gram[3 * BB * MID * MID]; // p0: F F^T, p1: G F^T, p2: G H^T
__device__ float g_s[BB];
__device__ __nv_bfloat16 g_Qhi[BB * CC * MID];   // Q = Wv M^T (UNSCALED)
__device__ __nv_bfloat16 g_Qlo[BB * CC * MID];
__device__ int g_cntA[BB];   // gram p0/p1 completion (target 32)
__device__ int g_cntB[BB];   // gv completion (target 16)
__device__ int g_cntC[BB];   // gram p2 completion (target 16)

// ---------------- PTX helpers ----------------
__device__ __forceinline__ uint32_t s2u(const void* p) {
    uint32_t a;
    asm("{ .reg .u64 t; cvta.to.shared.u64 t, %1; cvt.u32.u64 %0, t; }" : "=r"(a) : "l"(p));
    return a;
}

__device__ __forceinline__ void mma16816(float& c0, float& c1, float& c2, float& c3,
                                         uint32_t a0, uint32_t a1, uint32_t a2, uint32_t a3,
                                         uint32_t b0, uint32_t b1) {
    asm volatile(
        "mma.sync.aligned.m16n8k16.row.col.f32.bf16.bf16.f32 "
        "{%0,%1,%2,%3}, {%4,%5,%6,%7}, {%8,%9}, {%0,%1,%2,%3};"
        : "+f"(c0), "+f"(c1), "+f"(c2), "+f"(c3)
        : "r"(a0), "r"(a1), "r"(a2), "r"(a3), "r"(b0), "r"(b1));
}

#define LDSM4(r0, r1, r2, r3, addr) \
    asm volatile("ldmatrix.sync.aligned.m8n8.x4.shared.b16 {%0,%1,%2,%3}, [%4];" \
                 : "=r"(r0), "=r"(r1), "=r"(r2), "=r"(r3) : "r"(addr))

__device__ __forceinline__ uint32_t packbf(float f0, float f1) {
    __nv_bfloat162 h = __floats2bfloat162_rn(f0, f1);
    return *(uint32_t*)&h;
}

// 8 mma block: acc[2][4][4] += A(2 frags) x B(4 frags)
#define MMA_BLOCK(acc, a0, a1, b0, b1) do {                                   \
    mma16816(acc[0][0][0], acc[0][0][1], acc[0][0][2], acc[0][0][3],          \
             a0[0], a0[1], a0[2], a0[3], b0[0], b0[1]);                       \
    mma16816(acc[0][1][0], acc[0][1][1], acc[0][1][2], acc[0][1][3],          \
             a0[0], a0[1], a0[2], a0[3], b0[2], b0[3]);                       \
    mma16816(acc[0][2][0], acc[0][2][1], acc[0][2][2], acc[0][2][3],          \
             a0[0], a0[1], a0[2], a0[3], b1[0], b1[1]);                       \
    mma16816(acc[0][3][0], acc[0][3][1], acc[0][3][2], acc[0][3][3],          \
             a0[0], a0[1], a0[2], a0[3], b1[2], b1[3]);                       \
    mma16816(acc[1][0][0], acc[1][0][1], acc[1][0][2], acc[1][0][3],          \
             a1[0], a1[1], a1[2], a1[3], b0[0], b0[1]);                       \
    mma16816(acc[1][1][0], acc[1][1][1], acc[1][1][2], acc[1][1][3],          \
             a1[0], a1[1], a1[2], a1[3], b0[2], b0[3]);                       \
    mma16816(acc[1][2][0], acc[1][2][1], acc[1][2][2], acc[1][2][3],          \
             a1[0], a1[1], a1[2], a1[3], b1[0], b1[1]);                       \
    mma16816(acc[1][3][0], acc[1][3][1], acc[1][3][2], acc[1][3][3],          \
             a1[0], a1[1], a1[2], a1[3], b1[2], b1[3]);                       \
} while (0)

// Dedup'd 3-pass inner step: load 8 unique LDSM4, run 3 MMA blocks.
#define SPLIT3_STEP(acc, uAhi, uAlo, uBhi, uBlo, aoff, boff, kof) do {        \
    uint32_t ah0[4], ah1[4], al0[4], al1[4];                                  \
    uint32_t bh0[4], bh1[4], bl0[4], bl1[4];                                  \
    LDSM4(ah0[0], ah0[1], ah0[2], ah0[3], (uAhi) + (aoff) + (kof));           \
    LDSM4(ah1[0], ah1[1], ah1[2], ah1[3], (uAhi) + (aoff) + 16 * SB * 2 + (kof)); \
    LDSM4(bh0[0], bh0[1], bh0[2], bh0[3], (uBhi) + (boff) + (kof));           \
    LDSM4(bh1[0], bh1[1], bh1[2], bh1[3], (uBhi) + (boff) + 16 * SB * 2 + (kof)); \
    LDSM4(al0[0], al0[1], al0[2], al0[3], (uAlo) + (aoff) + (kof));           \
    LDSM4(al1[0], al1[1], al1[2], al1[3], (uAlo) + (aoff) + 16 * SB * 2 + (kof)); \
    LDSM4(bl0[0], bl0[1], bl0[2], bl0[3], (uBlo) + (boff) + (kof));           \
    LDSM4(bl1[0], bl1[1], bl1[2], bl1[3], (uBlo) + (boff) + 16 * SB * 2 + (kof)); \
    MMA_BLOCK(acc, ah0, ah1, bh0, bh1);                                       \
    MMA_BLOCK(acc, al0, al1, bh0, bh1);                                       \
    MMA_BLOCK(acc, ah0, ah1, bl0, bl1);                                       \
} while (0)

// ---------------- reductions ----------------
__device__ __forceinline__ float warpSum(float v) {
#pragma unroll
    for (int o = 16; o > 0; o >>= 1) v += __shfl_xor_sync(0xffffffffu, v, o);
    return v;
}

// ---------------- kernel 1: prep (BN fold + weight split) + xsplit fused ----
__global__ __launch_bounds__(256) void k_prepx(
        const float* __restrict__ x,
        const float* __restrict__ Wf, const float* __restrict__ bf,
        const float* __restrict__ gaf, const float* __restrict__ bef,
        const float* __restrict__ mef, const float* __restrict__ vaf,
        const float* __restrict__ Wg, const float* __restrict__ bg,
        const float* __restrict__ gag, const float* __restrict__ beg,
        const float* __restrict__ meg, const float* __restrict__ vag,
        const float* __restrict__ Wh, const float* __restrict__ bh) {
    int bid = blockIdx.x;
    int tid = threadIdx.x;
    if (bid >= 1024) {
        int idx = (bid - 1024) * 256 + tid;   // < 49152
        g_gram[idx] = 0.f;
        if (idx < BB) { g_cntA[idx] = 0; g_cntB[idx] = 0; g_cntC[idx] = 0; }
        int o = idx / CC, c = idx % CC;
        float w, bias;
        if (o < 64) {
            float inv = gaf[o] * rsqrtf(vaf[o] + EPSV);
            w = Wf[o * CC + c] * inv;
            bias = bf[o] * inv + bef[o] - mef[o] * inv;
        } else if (o < 128) {
            int oo = o - 64;
            float inv = gag[oo] * rsqrtf(vag[oo] + EPSV);
            w = Wg[oo * CC + c] * inv;
            bias = bg[oo] * inv + beg[oo] - meg[oo] * inv;
        } else {
            int oo = o - 128;
            w = Wh[oo * CC + c];
            bias = bh[oo];
        }
        __nv_bfloat16 hi = __float2bfloat16(w);
        __nv_bfloat16 lo = __float2bfloat16(w - __bfloat162float(hi));
        g_Whi[idx] = hi;
        g_Wlo[idx] = lo;
        if (c == 0) g_bcat[o] = bias;
        return;
    }
    __shared__ float ts[64][65];  // [n][c]
    int b = bid >> 8;
    int ct = ((bid >> 6) & 3) * 64, nt = (bid & 63) * 64;
    const float* xb = x + (size_t)b * CC * HWN;
#pragma unroll
    for (int i = 0; i < 4; i++) {
        int idx = i * 256 + tid;
        int c = idx >> 4, q = idx & 15;
        float4 v = *(const float4*)(xb + (size_t)(ct + c) * HWN + nt + q * 4);
        ts[q * 4 + 0][c] = v.x; ts[q * 4 + 1][c] = v.y;
        ts[q * 4 + 2][c] = v.z; ts[q * 4 + 3][c] = v.w;
    }
    __syncthreads();
#pragma unroll
    for (int i = 0; i < 8; i++) {
        int pidx = i * 256 + tid;
        int n = pidx >> 5, j = pidx & 31;
        float f0 = ts[n][2 * j], f1 = ts[n][2 * j + 1];
        __nv_bfloat16 h0 = __float2bfloat16(f0), h1 = __float2bfloat16(f1);
        float l0 = f0 - __bfloat162float(h0), l1 = f1 - __bfloat162float(h1);
        size_t o = ((size_t)b * HWN + nt + n) * CC + ct + 2 * j;
        __nv_bfloat162 hp; hp.x = h0; hp.y = h1;
        *(uint32_t*)(g_Xhi + o) = *(uint32_t*)&hp;
        *(uint32_t*)(g_Xlo + o) = packbf(l0, l1);
    }
}

// ---------------- kernel 2: FGH via mma.sync (dedup'd split passes) ---------
__global__ __launch_bounds__(256) void k_fgh_mma() {
    __shared__ __align__(16) char sbuf[33024];
    __nv_bfloat16* sp = (__nv_bfloat16*)sbuf;
    __nv_bfloat16* sWhi = sp;
    __nv_bfloat16* sWlo = sWhi + 64 * SB;
    __nv_bfloat16* sXhi = sWlo + 64 * SB;
    __nv_bfloat16* sXlo = sXhi + 128 * SB;
    float* fs = (float*)sbuf;                 // epilogue staging [64][129]

    int tid = threadIdx.x;
    int wid = tid >> 5, lane = tid & 31;
    int b = blockIdx.z, mt = blockIdx.y;
    int nbase = blockIdx.x * 128;
    int wm = wid & 1, wn = wid >> 1;

    uint32_t ub = s2u(sbuf);
    uint32_t uWhi = ub, uWlo = ub + 64 * SB * 2;
    uint32_t uXhi = uWlo + 64 * SB * 2, uXlo = uXhi + 128 * SB * 2;

    const __nv_bfloat16* Xh = g_Xhi + (size_t)b * HWN * CC;
    const __nv_bfloat16* Xl = g_Xlo + (size_t)b * HWN * CC;

    float acc[2][4][4];
#pragma unroll
    for (int i = 0; i < 2; i++)
#pragma unroll
        for (int j = 0; j < 4; j++)
#pragma unroll
            for (int q = 0; q < 4; q++) acc[i][j][q] = 0.f;

    uint32_t aoff = ((uint32_t)(wm * 32 + (lane & 15)) * SB + (lane >> 4) * 8) * 2;
    uint32_t boff = ((uint32_t)(wn * 32 + ((lane >> 4) & 1) * 8 + (lane & 7)) * SB
                     + ((lane >> 3) & 1) * 8) * 2;

    int arow = tid >> 2, auc = tid & 3;
    const __nv_bfloat16* srcW0 = g_Whi + (size_t)(mt * 64 + arow) * CC + auc * 8;
    const __nv_bfloat16* srcW1 = g_Wlo + (size_t)(mt * 64 + arow) * CC + auc * 8;
    const __nv_bfloat16* srcX0 = Xh + (size_t)(nbase + arow) * CC + auc * 8;
    const __nv_bfloat16* srcX1 = Xh + (size_t)(nbase + arow + 64) * CC + auc * 8;
    const __nv_bfloat16* srcX2 = Xl + (size_t)(nbase + arow) * CC + auc * 8;
    const __nv_bfloat16* srcX3 = Xl + (size_t)(nbase + arow + 64) * CC + auc * 8;

    uint4 pW0 = *(const uint4*)(srcW0);
    uint4 pW1 = *(const uint4*)(srcW1);
    uint4 pX0 = *(const uint4*)(srcX0);
    uint4 pX1 = *(const uint4*)(srcX1);
    uint4 pX2 = *(const uint4*)(srcX2);
    uint4 pX3 = *(const uint4*)(srcX3);

#pragma unroll 1
    for (int ki = 0; ki < CC / KC; ki++) {
        *(uint4*)(sWhi + arow * SB + auc * 8) = pW0;
        *(uint4*)(sWlo + arow * SB + auc * 8) = pW1;
        *(uint4*)(sXhi + arow * SB + auc * 8) = pX0;
        *(uint4*)(sXhi + (arow + 64) * SB + auc * 8) = pX1;
        *(uint4*)(sXlo + arow * SB + auc * 8) = pX2;
        *(uint4*)(sXlo + (arow + 64) * SB + auc * 8) = pX3;
        __syncthreads();
        if (ki < CC / KC - 1) {
            int kt = (ki + 1) * KC;
            pW0 = *(const uint4*)(srcW0 + kt);
            pW1 = *(const uint4*)(srcW1 + kt);
            pX0 = *(const uint4*)(srcX0 + kt);
            pX1 = *(const uint4*)(srcX1 + kt);
            pX2 = *(const uint4*)(srcX2 + kt);
            pX3 = *(const uint4*)(srcX3 + kt);
        }
#pragma unroll
        for (int ks = 0; ks < 2; ks++) {
            uint32_t kof = ks * 32;
            SPLIT3_STEP(acc, uWhi, uWlo, uXhi, uXlo, aoff, boff, kof);
        }
        __syncthreads();
    }

    int rq = lane >> 2;
    int cq = (lane & 3) * 2;
#pragma unroll
    for (int mf = 0; mf < 2; mf++) {
#pragma unroll
        for (int half = 0; half < 2; half++) {
            int orow = mt * 64 + wm * 32 + mf * 16 + rq + half * 8;
            float bias = g_bcat[orow];
            bool rl = (orow < 128);
            size_t base = ((size_t)b * 192 + orow) * HWN + nbase + wn * 32;
#pragma unroll
            for (int nf = 0; nf < 4; nf++) {
                float v0 = acc[mf][nf][half * 2 + 0] + bias;
                float v1 = acc[mf][nf][half * 2 + 1] + bias;
                if (rl) { v0 = fmaxf(v0, 0.f); v1 = fmaxf(v1, 0.f); }
                __nv_bfloat16 h0 = __float2bfloat16(v0), h1 = __float2bfloat16(v1);
                float l0 = v0 - __bfloat162float(h0), l1 = v1 - __bfloat162float(h1);
                __nv_bfloat162 hp; hp.x = h0; hp.y = h1;
                *(uint32_t*)(g_FGHkhi + base + nf * 8 + cq) = *(uint32_t*)&hp;
                *(uint32_t*)(g_FGHklo + base + nf * 8 + cq) = packbf(l0, l1);
            }
        }
    }

    // mt==0: emit F^T bf16 hi/lo (holds all 64 F rows)
    if (mt == 0) {
        __syncthreads();
#pragma unroll
        for (int mf = 0; mf < 2; mf++)
#pragma unroll
            for (int half = 0; half < 2; half++) {
                int k = wm * 32 + mf * 16 + rq + half * 8;
                float bias = g_bcat[k];
#pragma unroll
                for (int nf = 0; nf < 4; nf++) {
                    int n = wn * 32 + nf * 8 + cq;
                    fs[k * 129 + n] = fmaxf(acc[mf][nf][half * 2 + 0] + bias, 0.f);
                    fs[k * 129 + n + 1] = fmaxf(acc[mf][nf][half * 2 + 1] + bias, 0.f);
                }
            }
        __syncthreads();
#pragma unroll
        for (int i = 0; i < 16; i++) {
            int pidx = i * 256 + tid;
            int n = pidx >> 5, j = pidx & 31;
            float f0 = fs[(2 * j) * 129 + n], f1 = fs[(2 * j + 1) * 129 + n];
            __nv_bfloat16 h0 = __float2bfloat16(f0), h1 = __float2bfloat16(f1);
            float l0 = f0 - __bfloat162float(h0), l1 = f1 - __bfloat162float(h1);
            size_t o = ((size_t)b * HWN + nbase + n) * MID + 2 * j;
            __nv_bfloat162 hp; hp.x = h0; hp.y = h1;
            *(uint32_t*)(g_Fthi + o) = *(uint32_t*)&hp;
            *(uint32_t*)(g_Ftlo + o) = packbf(l0, l1);
        }
    }
}

// ---------------- kernel 3: Gram + gv + Q + s (device-side completion) ------
// grid (BB, 4, 16), 128 thr.
//  p<2 : gram p over 8 n-chunks of 32 (atomics), bump cntA.
//  p==2: gram p2, bump cntC.
//  p==3: gv for k=z*4+wid, bump cntB; spin cntC==16; compute Q rows
//        [z*16, z*16+16); z==15 also spins cntA==32 & cntB==16 and computes s.
__global__ __launch_bounds__(128) void k_gramgv(const float* __restrict__ v0,
                                                const float* __restrict__ Wv) {
    __shared__ __align__(16) char sgbuf[21504];
    int tid = threadIdx.x;
    int wid = tid >> 5, lane = tid & 31;
    int b = blockIdx.x, p = blockIdx.y, z = blockIdx.z;

    if (p == 3) {
        float* Mt = (float*)sgbuf;                    // [64][65] = 16640 B
        float* Ws = (float*)(sgbuf + 16640);          // [16][64] = 4096 B
        float* gvs = (float*)(sgbuf + 20736);         // 64 floats
        // gv
        int k = z * 4 + wid;
        const __nv_bfloat16* rh = g_FGHkhi + ((size_t)b * 192 + 64 + k) * HWN;
        const __nv_bfloat16* rl = g_FGHklo + ((size_t)b * 192 + 64 + k) * HWN;
        const float* v = v0 + (size_t)b * HWN;
        float s = 0.f;
#pragma unroll 4
        for (int it = 0; it < 16; it++) {
            int n0 = (it * 32 + lane) * 8;
            uint4 hu = *(const uint4*)(rh + n0);
            uint4 lu = *(const uint4*)(rl + n0);
            float4 va = *(const float4*)(v + n0);
            float4 vb = *(const float4*)(v + n0 + 4);
            uint32_t hw[4] = {hu.x, hu.y, hu.z, hu.w};
            uint32_t lw[4] = {lu.x, lu.y, lu.z, lu.w};
            float vv[8] = {va.x, va.y, va.z, va.w, vb.x, vb.y, vb.z, vb.w};
#pragma unroll
            for (int j = 0; j < 4; j++) {
                float2 hf = __bfloat1622float2(*(__nv_bfloat162*)&hw[j]);
                float2 lf = __bfloat1622float2(*(__nv_bfloat162*)&lw[j]);
                s += (hf.x + lf.x) * vv[2 * j] + (hf.y + lf.y) * vv[2 * j + 1];
            }
        }
        s = warpSum(s);
        if (lane == 0) g_gv[b * MID + k] = s;
        __threadfence();
        __syncthreads();
        if (tid == 0) atomicAdd(&g_cntB[b], 1);

        // spin for gram p2 (Q inputs); z==15 also for grams p0/p1 + all gv
        if (tid == 0) {
            if (z == 15) {
                while (atomicAdd(&g_cntC[b], 0) < 16 ||
                       atomicAdd(&g_cntA[b], 0) < 32 ||
                       atomicAdd(&g_cntB[b], 0) < 16) {}
            } else {
                while (atomicAdd(&g_cntC[b], 0) < 16) {}
            }
        }
        __syncthreads();
        __threadfence();

        // Q rows [z*16, z*16+16): Q[o][k] = sum_c Wv[o][c]*M[k][c]
        const float* Mb = g_gram + ((size_t)2 * BB + b) * MID * MID;
#pragma unroll
        for (int i = 0; i < 32; i++) {
            int idx = i * 128 + tid;          // [0,4096)
            int kk = idx >> 6, c = idx & 63;
            Mt[c * 65 + kk] = __ldcg(Mb + idx);
        }
#pragma unroll
        for (int i = 0; i < 8; i++) {
            int idx = i * 128 + tid;          // [0,1024)
            Ws[idx] = Wv[(size_t)z * 16 * MID + idx];
        }
        __syncthreads();
        {
            int r = tid >> 3;                 // 0..15
            int c8 = (tid & 7) * 8;
            float qa[8] = {};
#pragma unroll
            for (int c = 0; c < 64; c++) {
                float w = Ws[r * 64 + c];
                const float* mp = Mt + c * 65 + c8;
#pragma unroll
                for (int j = 0; j < 8; j++) qa[j] += w * mp[j];
            }
            int orow = z * 16 + r;
            size_t off = ((size_t)b * CC + orow) * MID + c8;
#pragma unroll
            for (int j = 0; j < 8; j += 2) {
                __nv_bfloat16 h0 = __float2bfloat16(qa[j]);
                __nv_bfloat16 h1 = __float2bfloat16(qa[j + 1]);
                float l0 = qa[j] - __bfloat162float(h0);
                float l1 = qa[j + 1] - __bfloat162float(h1);
                __nv_bfloat162 hp; hp.x = h0; hp.y = h1;
                *(uint32_t*)(g_Qhi + off + j) = *(uint32_t*)&hp;
                *(uint32_t*)(g_Qlo + off + j) = packbf(l0, l1);
            }
        }

        // z==15: s = (fv . gvv)/(gv . fv), fv=(F F^T)gv, gvv=(G F^T)gv
        if (z == 15) {
            __shared__ float fvs[64], gvvs[64];
            if (tid < 64) gvs[tid] = __ldcg(&g_gv[b * MID + tid]);
            __syncthreads();
            {
                int row = tid;                // 0..127
                int pm = (row < 64) ? 0 : 1;
                int rl2 = row & 63;
                const float* A = g_gram + ((size_t)pm * BB + b) * MID * MID + rl2 * MID;
                float ps = 0.f;
#pragma unroll
                for (int j = 0; j < 64; j++) ps += __ldcg(A + j) * gvs[j];
                if (row < 64) fvs[rl2] = ps; else gvvs[rl2] = ps;
            }
            __syncthreads();
            if (tid < 32) {
                float ss = fvs[tid] * gvs[tid] + fvs[tid + 32] * gvs[tid + 32];
                float num = fvs[tid] * gvvs[tid] + fvs[tid + 32] * gvvs[tid + 32];
                ss = warpSum(ss);
                num = warpSum(num);
                if (tid == 0) g_s[b] = num / ss;
            }
        }
        return;
    }

    __nv_bfloat16* sg = (__nv_bfloat16*)sgbuf;
    __nv_bfloat16* sAhi = sg;
    __nv_bfloat16* sAlo = sAhi + 64 * SB;
    __nv_bfloat16* sBhi = sAlo + 64 * SB;
    __nv_bfloat16* sBlo = sBhi + 64 * SB;
    uint32_t ub = s2u(sgbuf);
    uint32_t uAhi = ub, uAlo = ub + 64 * SB * 2;
    uint32_t uBhi = uAlo + 64 * SB * 2, uBlo = uBhi + 64 * SB * 2;

    int aroff = (p == 0) ? 0 : 64;
    int broff = (p == 2) ? 128 : 0;
    int wi = wid & 1, wj = wid >> 1;

    float acc[2][4][4];
#pragma unroll
    for (int i = 0; i < 2; i++)
#pragma unroll
        for (int j = 0; j < 4; j++)
#pragma unroll
            for (int q = 0; q < 4; q++) acc[i][j][q] = 0.f;

    uint32_t aoff = ((uint32_t)(wi * 32 + (lane & 15)) * SB + (lane >> 4) * 8) * 2;
    uint32_t boff = ((uint32_t)(wj * 32 + ((lane >> 4) & 1) * 8 + (lane & 7)) * SB
                     + ((lane >> 3) & 1) * 8) * 2;

#pragma unroll 1
    for (int l = 0; l < 8; l++) {
        int nb = z * 256 + l * 32;
#pragma unroll
        for (int i = 0; i < 2; i++) {
            int unit = i * 128 + tid;      // 256 units = 64 rows x 4 uint4
            int row = unit >> 2, uc = unit & 3;
            size_t ga = ((size_t)b * 192 + aroff + row) * HWN + nb + uc * 8;
            size_t gb = ((size_t)b * 192 + broff + row) * HWN + nb + uc * 8;
            *(uint4*)(sAhi + row * SB + uc * 8) = *(const uint4*)(g_FGHkhi + ga);
            *(uint4*)(sAlo + row * SB + uc * 8) = *(const uint4*)(g_FGHklo + ga);
            *(uint4*)(sBhi + row * SB + uc * 8) = *(const uint4*)(g_FGHkhi + gb);
            *(uint4*)(sBlo + row * SB + uc * 8) = *(const uint4*)(g_FGHklo + gb);
        }
        __syncthreads();
#pragma unroll
        for (int ks = 0; ks < 2; ks++) {
            uint32_t kof = ks * 32;
            SPLIT3_STEP(acc, uAhi, uAlo, uBhi, uBlo, aoff, boff, kof);
        }
        __syncthreads();
    }

    float* dst = g_gram + ((size_t)p * BB + b) * MID * MID;
    int rq = lane >> 2, cq = (lane & 3) * 2;
#pragma unroll
    for (int mf = 0; mf < 2; mf++)
#pragma unroll
        for (int half = 0; half < 2; half++) {
            int i = wi * 32 + mf * 16 + rq + half * 8;
#pragma unroll
            for (int nf = 0; nf < 4; nf++) {
                int j = wj * 32 + nf * 8 + cq;
                atomicAdd(&dst[i * MID + j], acc[mf][nf][half * 2 + 0]);
                atomicAdd(&dst[i * MID + j + 1], acc[mf][nf][half * 2 + 1]);
            }
        }
    __threadfence();
    __syncthreads();
    if (tid == 0) {
        if (p < 2) atomicAdd(&g_cntA[b], 1);
        else atomicAdd(&g_cntC[b], 1);
    }
}

// ---------------- kernel 4: out = (1/s) Q @ F + bv + x (R12 version) --------
__global__ __launch_bounds__(256) void k_out_mma(const float* __restrict__ x,
                                                 const float* __restrict__ bv,
                                                 float* __restrict__ out) {
    __shared__ __align__(16) char sbuf[30720];
    __nv_bfloat16* sp = (__nv_bfloat16*)sbuf;
    __nv_bfloat16* sAhi = sp;
    __nv_bfloat16* sAlo = sAhi + 64 * SB;
    __nv_bfloat16* sBhi = sAlo + 64 * SB;
    __nv_bfloat16* sBlo = sBhi + 128 * SB;

    int tid = threadIdx.x;
    int wid = tid >> 5, lane = tid & 31;
    int b = blockIdx.z, mt = blockIdx.y;
    int nbase = blockIdx.x * 128;
    int wm = wid & 1, wn = wid >> 1;

    uint32_t ub = s2u(sbuf);
    uint32_t uAhi = ub, uAlo = ub + 64 * SB * 2;
    uint32_t uBhi = uAlo + 64 * SB * 2, uBlo = uBhi + 128 * SB * 2;

    float acc[2][4][4];
#pragma unroll
    for (int i = 0; i < 2; i++)
#pragma unroll
        for (int j = 0; j < 4; j++)
#pragma unroll
            for (int q = 0; q < 4; q++) acc[i][j][q] = 0.f;

    uint32_t aoff = ((uint32_t)(wm * 32 + (lane & 15)) * SB + (lane >> 4) * 8) * 2;
    uint32_t boff = ((uint32_t)(wn * 32 + ((lane >> 4) & 1) * 8 + (lane & 7)) * SB
                     + ((lane >> 3) & 1) * 8) * 2;

    int arow = tid >> 2, auc = tid & 3;
    const __nv_bfloat16* srcA0 = g_Qhi + ((size_t)b * CC + mt * 64 + arow) * MID + auc * 8;
    const __nv_bfloat16* srcA1 = g_Qlo + ((size_t)b * CC + mt * 64 + arow) * MID + auc * 8;
    const __nv_bfloat16* srcB0 = g_Fthi + ((size_t)b * HWN + nbase + arow) * MID + auc * 8;
    const __nv_bfloat16* srcB1 = g_Fthi + ((size_t)b * HWN + nbase + arow + 64) * MID + auc * 8;
    const __nv_bfloat16* srcB2 = g_Ftlo + ((size_t)b * HWN + nbase + arow) * MID + auc * 8;
    const __nv_bfloat16* srcB3 = g_Ftlo + ((size_t)b * HWN + nbase + arow + 64) * MID + auc * 8;

    uint4 pA0 = *(const uint4*)(srcA0);
    uint4 pA1 = *(const uint4*)(srcA1);
    uint4 pB0 = *(const uint4*)(srcB0);
    uint4 pB1 = *(const uint4*)(srcB1);
    uint4 pB2 = *(const uint4*)(srcB2);
    uint4 pB3 = *(const uint4*)(srcB3);

#pragma unroll 1
    for (int ki = 0; ki < MID / KC; ki++) {
        *(uint4*)(sAhi + arow * SB + auc * 8) = pA0;
        *(uint4*)(sAlo + arow * SB + auc * 8) = pA1;
        *(uint4*)(sBhi + arow * SB + auc * 8) = pB0;
        *(uint4*)(sBhi + (arow + 64) * SB + auc * 8) = pB1;
        *(uint4*)(sBlo + arow * SB + auc * 8) = pB2;
        *(uint4*)(sBlo + (arow + 64) * SB + auc * 8) = pB3;
        __syncthreads();
        if (ki < MID / KC - 1) {
            int kt = (ki + 1) * KC;
            pA0 = *(const uint4*)(srcA0 + kt);
            pA1 = *(const uint4*)(srcA1 + kt);
            pB0 = *(const uint4*)(srcB0 + kt);
            pB1 = *(const uint4*)(srcB1 + kt);
            pB2 = *(const uint4*)(srcB2 + kt);
            pB3 = *(const uint4*)(srcB3 + kt);
        }
#pragma unroll
        for (int ks = 0; ks < 2; ks++) {
            uint32_t kof = ks * 32;
            SPLIT3_STEP(acc, uAhi, uAlo, uBhi, uBlo, aoff, boff, kof);
        }
        __syncthreads();
    }

    float inv_s = 1.f / g_s[b];
    int rq = lane >> 2;
    int cq = (lane & 3) * 2;
#pragma unroll
    for (int mf = 0; mf < 2; mf++) {
#pragma unroll
        for (int half = 0; half < 2; half++) {
            int orow = mt * 64 + wm * 32 + mf * 16 + rq + half * 8;
            float bias = bv[orow];
            size_t rowoff = ((size_t)b * CC + orow) * HWN + nbase + wn * 32;
#pragma unroll
            for (int nf = 0; nf < 4; nf++) {
                size_t off = rowoff + nf * 8 + cq;
                float2 xr = *(const float2*)(x + off);
                float2 v;
                v.x = acc[mf][nf][half * 2 + 0] * inv_s + bias + xr.x;
                v.y = acc[mf][nf][half * 2 + 1] * inv_s + bias + xr.y;
                *(float2*)(out + off) = v;
            }
        }
    }
}

// ---------------- launch ----------------
extern "C" void kernel_launch(void* const* d_in, const int* in_sizes, int n_in,
                              void* d_out, int out_size) {
    (void)in_sizes; (void)n_in; (void)out_size;
    const float* x   = (const float*)d_in[0];
    const float* Wf  = (const float*)d_in[1];
    const float* bf  = (const float*)d_in[2];
    const float* gaf = (const float*)d_in[3];
    const float* bef = (const float*)d_in[4];
    const float* mef = (const float*)d_in[5];
    const float* vaf = (const float*)d_in[6];
    const float* Wg  = (const float*)d_in[7];
    const float* bg  = (const float*)d_in[8];
    const float* gag = (const float*)d_in[9];
    const float* beg = (const float*)d_in[10];
    const float* meg = (const float*)d_in[11];
    const float* vag = (const float*)d_in[12];
    const float* Wh  = (const float*)d_in[13];
    const float* bh  = (const float*)d_in[14];
    const float* Wv  = (const float*)d_in[15];
    const float* bv  = (const float*)d_in[16];
    const float* v0  = (const float*)d_in[17];
    float* out = (float*)d_out;

    k_prepx<<<1024 + 192, 256>>>(x, Wf, bf, gaf, bef, mef, vaf,
                                 Wg, bg, gag, beg, meg, vag, Wh, bh);
    k_fgh_mma<<<dim3(HWN / 128, 3, BB), 256>>>();
    k_gramgv<<<dim3(BB, 4, 16), 128>>>(v0, Wv);
    k_out_mma<<<dim3(HWN / 128, 4, BB), 256>>>(x, bv, out);
}

// round 15
// speedup vs baseline: 1.1533x; 1.0954x over previous
#include <cuda_runtime.h>
#include <cuda_bf16.h>
#include <cstdint>
#include <stdint.h>
#include <math.h>

#define BB 4
#define CC 256
#define MID 64
#define HWN 4096
#define EPSV 1e-5f
#define KC 32
#define SB 40      // smem row stride in bf16 (80B; ldmatrix conflict-free)

// ---------------- scratch (device globals; no allocation allowed) ----------
__device__ __nv_bfloat16 g_Whi[192 * CC];
__device__ __nv_bfloat16 g_Wlo[192 * CC];
__device__ float g_bcat[192];
__device__ __nv_bfloat16 g_Xhi[(size_t)BB * HWN * CC];  // x^T bf16 hi: [b][n][c]
__device__ __nv_bfloat16 g_Xlo[(size_t)BB * HWN * CC];
__device__ __nv_bfloat16 g_FGHkhi[(size_t)BB * 192 * HWN]; // FGH bf16 hi: [b][r][n]
__device__ __nv_bfloat16 g_FGHklo[(size_t)BB * 192 * HWN]; // FGH bf16 lo
__device__ __nv_bfloat16 g_Fthi[(size_t)BB * HWN * MID]; // F^T: [b][n][k]
__device__ __nv_bfloat16 g_Ftlo[(size_t)BB * HWN * MID];
__device__ float g_gv[BB * MID];
__device__ float g_gram[3 * BB * MID * MID]; // p0: F F^T, p1: G F^T, p2: G H^T
__device__ float g_s[BB];
__device__ __nv_bfloat16 g_Qhi[BB * CC * MID];   // Q = Wv M^T (UNSCALED)
__device__ __nv_bfloat16 g_Qlo[BB * CC * MID];

// ---------------- PTX helpers ----------------
__device__ __forceinline__ uint32_t s2u(const void* p) {
    uint32_t a;
    asm("{ .reg .u64 t; cvta.to.shared.u64 t, %1; cvt.u32.u64 %0, t; }" : "=r"(a) : "l"(p));
    return a;
}

__device__ __forceinline__ void mma16816(float& c0, float& c1, float& c2, float& c3,
                                         uint32_t a0, uint32_t a1, uint32_t a2, uint32_t a3,
                                         uint32_t b0, uint32_t b1) {
    asm volatile(
        "mma.sync.aligned.m16n8k16.row.col.f32.bf16.bf16.f32 "
        "{%0,%1,%2,%3}, {%4,%5,%6,%7}, {%8,%9}, {%0,%1,%2,%3};"
        : "+f"(c0), "+f"(c1), "+f"(c2), "+f"(c3)
        : "r"(a0), "r"(a1), "r"(a2), "r"(a3), "r"(b0), "r"(b1));
}

#define LDSM4(r0, r1, r2, r3, addr) \
    asm volatile("ldmatrix.sync.aligned.m8n8.x4.shared.b16 {%0,%1,%2,%3}, [%4];" \
                 : "=r"(r0), "=r"(r1), "=r"(r2), "=r"(r3) : "r"(addr))

__device__ __forceinline__ uint32_t packbf(float f0, float f1) {
    __nv_bfloat162 h = __floats2bfloat162_rn(f0, f1);
    return *(uint32_t*)&h;
}

// 8 mma block: acc[2][4][4] += A(2 frags) x B(4 frags)
#define MMA_BLOCK(acc, a0, a1, b0, b1) do {                                   \
    mma16816(acc[0][0][0], acc[0][0][1], acc[0][0][2], acc[0][0][3],          \
             a0[0], a0[1], a0[2], a0[3], b0[0], b0[1]);                       \
    mma16816(acc[0][1][0], acc[0][1][1], acc[0][1][2], acc[0][1][3],          \
             a0[0], a0[1], a0[2], a0[3], b0[2], b0[3]);                       \
    mma16816(acc[0][2][0], acc[0][2][1], acc[0][2][2], acc[0][2][3],          \
             a0[0], a0[1], a0[2], a0[3], b1[0], b1[1]);                       \
    mma16816(acc[0][3][0], acc[0][3][1], acc[0][3][2], acc[0][3][3],          \
             a0[0], a0[1], a0[2], a0[3], b1[2], b1[3]);                       \
    mma16816(acc[1][0][0], acc[1][0][1], acc[1][0][2], acc[1][0][3],          \
             a1[0], a1[1], a1[2], a1[3], b0[0], b0[1]);                       \
    mma16816(acc[1][1][0], acc[1][1][1], acc[1][1][2], acc[1][1][3],          \
             a1[0], a1[1], a1[2], a1[3], b0[2], b0[3]);                       \
    mma16816(acc[1][2][0], acc[1][2][1], acc[1][2][2], acc[1][2][3],          \
             a1[0], a1[1], a1[2], a1[3], b1[0], b1[1]);                       \
    mma16816(acc[1][3][0], acc[1][3][1], acc[1][3][2], acc[1][3][3],          \
             a1[0], a1[1], a1[2], a1[3], b1[2], b1[3]);                       \
} while (0)

// Dedup'd 3-pass inner step: load 8 unique LDSM4, run 3 MMA blocks.
#define SPLIT3_STEP(acc, uAhi, uAlo, uBhi, uBlo, aoff, boff, kof) do {        \
    uint32_t ah0[4], ah1[4], al0[4], al1[4];                                  \
    uint32_t bh0[4], bh1[4], bl0[4], bl1[4];                                  \
    LDSM4(ah0[0], ah0[1], ah0[2], ah0[3], (uAhi) + (aoff) + (kof));           \
    LDSM4(ah1[0], ah1[1], ah1[2], ah1[3], (uAhi) + (aoff) + 16 * SB * 2 + (kof)); \
    LDSM4(bh0[0], bh0[1], bh0[2], bh0[3], (uBhi) + (boff) + (kof));           \
    LDSM4(bh1[0], bh1[1], bh1[2], bh1[3], (uBhi) + (boff) + 16 * SB * 2 + (kof)); \
    LDSM4(al0[0], al0[1], al0[2], al0[3], (uAlo) + (aoff) + (kof));           \
    LDSM4(al1[0], al1[1], al1[2], al1[3], (uAlo) + (aoff) + 16 * SB * 2 + (kof)); \
    LDSM4(bl0[0], bl0[1], bl0[2], bl0[3], (uBlo) + (boff) + (kof));           \
    LDSM4(bl1[0], bl1[1], bl1[2], bl1[3], (uBlo) + (boff) + 16 * SB * 2 + (kof)); \
    MMA_BLOCK(acc, ah0, ah1, bh0, bh1);                                       \
    MMA_BLOCK(acc, al0, al1, bh0, bh1);                                       \
    MMA_BLOCK(acc, ah0, ah1, bl0, bl1);                                       \
} while (0)

// ---------------- reductions ----------------
__device__ __forceinline__ float warpSum(float v) {
#pragma unroll
    for (int o = 16; o > 0; o >>= 1) v += __shfl_xor_sync(0xffffffffu, v, o);
    return v;
}

// ---------------- kernel 1: prep (BN fold + weight split) + xsplit fused ----
__global__ __launch_bounds__(256) void k_prepx(
        const float* __restrict__ x,
        const float* __restrict__ Wf, const float* __restrict__ bf,
        const float* __restrict__ gaf, const float* __restrict__ bef,
        const float* __restrict__ mef, const float* __restrict__ vaf,
        const float* __restrict__ Wg, const float* __restrict__ bg,
        const float* __restrict__ gag, const float* __restrict__ beg,
        const float* __restrict__ meg, const float* __restrict__ vag,
        const float* __restrict__ Wh, const float* __restrict__ bh) {
    int bid = blockIdx.x;
    int tid = threadIdx.x;
    if (bid >= 1024) {
        int idx = (bid - 1024) * 256 + tid;   // < 49152
        g_gram[idx] = 0.f;
        int o = idx / CC, c = idx % CC;
        float w, bias;
        if (o < 64) {
            float inv = gaf[o] * rsqrtf(vaf[o] + EPSV);
            w = Wf[o * CC + c] * inv;
            bias = bf[o] * inv + bef[o] - mef[o] * inv;
        } else if (o < 128) {
            int oo = o - 64;
            float inv = gag[oo] * rsqrtf(vag[oo] + EPSV);
            w = Wg[oo * CC + c] * inv;
            bias = bg[oo] * inv + beg[oo] - meg[oo] * inv;
        } else {
            int oo = o - 128;
            w = Wh[oo * CC + c];
            bias = bh[oo];
        }
        __nv_bfloat16 hi = __float2bfloat16(w);
        __nv_bfloat16 lo = __float2bfloat16(w - __bfloat162float(hi));
        g_Whi[idx] = hi;
        g_Wlo[idx] = lo;
        if (c == 0) g_bcat[o] = bias;
        return;
    }
    __shared__ float ts[64][65];  // [n][c]
    int b = bid >> 8;
    int ct = ((bid >> 6) & 3) * 64, nt = (bid & 63) * 64;
    const float* xb = x + (size_t)b * CC * HWN;
#pragma unroll
    for (int i = 0; i < 4; i++) {
        int idx = i * 256 + tid;
        int c = idx >> 4, q = idx & 15;
        float4 v = *(const float4*)(xb + (size_t)(ct + c) * HWN + nt + q * 4);
        ts[q * 4 + 0][c] = v.x; ts[q * 4 + 1][c] = v.y;
        ts[q * 4 + 2][c] = v.z; ts[q * 4 + 3][c] = v.w;
    }
    __syncthreads();
#pragma unroll
    for (int i = 0; i < 8; i++) {
        int pidx = i * 256 + tid;
        int n = pidx >> 5, j = pidx & 31;
        float f0 = ts[n][2 * j], f1 = ts[n][2 * j + 1];
        __nv_bfloat16 h0 = __float2bfloat16(f0), h1 = __float2bfloat16(f1);
        float l0 = f0 - __bfloat162float(h0), l1 = f1 - __bfloat162float(h1);
        size_t o = ((size_t)b * HWN + nt + n) * CC + ct + 2 * j;
        __nv_bfloat162 hp; hp.x = h0; hp.y = h1;
        *(uint32_t*)(g_Xhi + o) = *(uint32_t*)&hp;
        *(uint32_t*)(g_Xlo + o) = packbf(l0, l1);
    }
}

// ---------------- kernel 2: FGH via mma.sync (dedup'd split passes) ---------
__global__ __launch_bounds__(256) void k_fgh_mma() {
    __shared__ __align__(16) char sbuf[33024];
    __nv_bfloat16* sp = (__nv_bfloat16*)sbuf;
    __nv_bfloat16* sWhi = sp;
    __nv_bfloat16* sWlo = sWhi + 64 * SB;
    __nv_bfloat16* sXhi = sWlo + 64 * SB;
    __nv_bfloat16* sXlo = sXhi + 128 * SB;
    float* fs = (float*)sbuf;                 // epilogue staging [64][129]

    int tid = threadIdx.x;
    int wid = tid >> 5, lane = tid & 31;
    int b = blockIdx.z, mt = blockIdx.y;
    int nbase = blockIdx.x * 128;
    int wm = wid & 1, wn = wid >> 1;

    uint32_t ub = s2u(sbuf);
    uint32_t uWhi = ub, uWlo = ub + 64 * SB * 2;
    uint32_t uXhi = uWlo + 64 * SB * 2, uXlo = uXhi + 128 * SB * 2;

    const __nv_bfloat16* Xh = g_Xhi + (size_t)b * HWN * CC;
    const __nv_bfloat16* Xl = g_Xlo + (size_t)b * HWN * CC;

    float acc[2][4][4];
#pragma unroll
    for (int i = 0; i < 2; i++)
#pragma unroll
        for (int j = 0; j < 4; j++)
#pragma unroll
            for (int q = 0; q < 4; q++) acc[i][j][q] = 0.f;

    uint32_t aoff = ((uint32_t)(wm * 32 + (lane & 15)) * SB + (lane >> 4) * 8) * 2;
    uint32_t boff = ((uint32_t)(wn * 32 + ((lane >> 4) & 1) * 8 + (lane & 7)) * SB
                     + ((lane >> 3) & 1) * 8) * 2;

    int arow = tid >> 2, auc = tid & 3;
    const __nv_bfloat16* srcW0 = g_Whi + (size_t)(mt * 64 + arow) * CC + auc * 8;
    const __nv_bfloat16* srcW1 = g_Wlo + (size_t)(mt * 64 + arow) * CC + auc * 8;
    const __nv_bfloat16* srcX0 = Xh + (size_t)(nbase + arow) * CC + auc * 8;
    const __nv_bfloat16* srcX1 = Xh + (size_t)(nbase + arow + 64) * CC + auc * 8;
    const __nv_bfloat16* srcX2 = Xl + (size_t)(nbase + arow) * CC + auc * 8;
    const __nv_bfloat16* srcX3 = Xl + (size_t)(nbase + arow + 64) * CC + auc * 8;

#pragma unroll 1
    for (int ki = 0; ki < CC / KC; ki++) {
        int kt = ki * KC;
        *(uint4*)(sWhi + arow * SB + auc * 8) = *(const uint4*)(srcW0 + kt);
        *(uint4*)(sWlo + arow * SB + auc * 8) = *(const uint4*)(srcW1 + kt);
        *(uint4*)(sXhi + arow * SB + auc * 8) = *(const uint4*)(srcX0 + kt);
        *(uint4*)(sXhi + (arow + 64) * SB + auc * 8) = *(const uint4*)(srcX1 + kt);
        *(uint4*)(sXlo + arow * SB + auc * 8) = *(const uint4*)(srcX2 + kt);
        *(uint4*)(sXlo + (arow + 64) * SB + auc * 8) = *(const uint4*)(srcX3 + kt);
        __syncthreads();
#pragma unroll
        for (int ks = 0; ks < 2; ks++) {
            uint32_t kof = ks * 32;
            SPLIT3_STEP(acc, uWhi, uWlo, uXhi, uXlo, aoff, boff, kof);
        }
        __syncthreads();
    }

    int rq = lane >> 2;
    int cq = (lane & 3) * 2;
#pragma unroll
    for (int mf = 0; mf < 2; mf++) {
#pragma unroll
        for (int half = 0; half < 2; half++) {
            int orow = mt * 64 + wm * 32 + mf * 16 + rq + half * 8;
            float bias = g_bcat[orow];
            bool rl = (orow < 128);
            size_t base = ((size_t)b * 192 + orow) * HWN + nbase + wn * 32;
#pragma unroll
            for (int nf = 0; nf < 4; nf++) {
                float v0 = acc[mf][nf][half * 2 + 0] + bias;
                float v1 = acc[mf][nf][half * 2 + 1] + bias;
                if (rl) { v0 = fmaxf(v0, 0.f); v1 = fmaxf(v1, 0.f); }
                __nv_bfloat16 h0 = __float2bfloat16(v0), h1 = __float2bfloat16(v1);
                float l0 = v0 - __bfloat162float(h0), l1 = v1 - __bfloat162float(h1);
                __nv_bfloat162 hp; hp.x = h0; hp.y = h1;
                *(uint32_t*)(g_FGHkhi + base + nf * 8 + cq) = *(uint32_t*)&hp;
                *(uint32_t*)(g_FGHklo + base + nf * 8 + cq) = packbf(l0, l1);
            }
        }
    }

    // mt==0: emit F^T bf16 hi/lo (holds all 64 F rows)
    if (mt == 0) {
        __syncthreads();
#pragma unroll
        for (int mf = 0; mf < 2; mf++)
#pragma unroll
            for (int half = 0; half < 2; half++) {
                int k = wm * 32 + mf * 16 + rq + half * 8;
                float bias = g_bcat[k];
#pragma unroll
                for (int nf = 0; nf < 4; nf++) {
                    int n = wn * 32 + nf * 8 + cq;
                    fs[k * 129 + n] = fmaxf(acc[mf][nf][half * 2 + 0] + bias, 0.f);
                    fs[k * 129 + n + 1] = fmaxf(acc[mf][nf][half * 2 + 1] + bias, 0.f);
                }
            }
        __syncthreads();
#pragma unroll
        for (int i = 0; i < 16; i++) {
            int pidx = i * 256 + tid;
            int n = pidx >> 5, j = pidx & 31;
            float f0 = fs[(2 * j) * 129 + n], f1 = fs[(2 * j + 1) * 129 + n];
            __nv_bfloat16 h0 = __float2bfloat16(f0), h1 = __float2bfloat16(f1);
            float l0 = f0 - __bfloat162float(h0), l1 = f1 - __bfloat162float(h1);
            size_t o = ((size_t)b * HWN + nbase + n) * MID + 2 * j;
            __nv_bfloat162 hp; hp.x = h0; hp.y = h1;
            *(uint32_t*)(g_Fthi + o) = *(uint32_t*)&hp;
            *(uint32_t*)(g_Ftlo + o) = packbf(l0, l1);
        }
    }
}

// ---------------- kernel 3: Gram products via mma + fused gv ----------------
__global__ __launch_bounds__(128) void k_gramgv(const float* __restrict__ v0) {
    __shared__ __align__(16) __nv_bfloat16 sg[4 * 64 * SB];
    int tid = threadIdx.x;
    int wid = tid >> 5, lane = tid & 31;
    int b = blockIdx.x, p = blockIdx.y, z = blockIdx.z;

    if (p == 3) {
        int k = z * 4 + wid;
        const __nv_bfloat16* rh = g_FGHkhi + ((size_t)b * 192 + 64 + k) * HWN;
        const __nv_bfloat16* rl = g_FGHklo + ((size_t)b * 192 + 64 + k) * HWN;
        const float* v = v0 + (size_t)b * HWN;
        float s = 0.f;
#pragma unroll 4
        for (int it = 0; it < 16; it++) {
            int n0 = (it * 32 + lane) * 8;
            uint4 hu = *(const uint4*)(rh + n0);
            uint4 lu = *(const uint4*)(rl + n0);
            float4 va = *(const float4*)(v + n0);
            float4 vb = *(const float4*)(v + n0 + 4);
            uint32_t hw[4] = {hu.x, hu.y, hu.z, hu.w};
            uint32_t lw[4] = {lu.x, lu.y, lu.z, lu.w};
            float vv[8] = {va.x, va.y, va.z, va.w, vb.x, vb.y, vb.z, vb.w};
#pragma unroll
            for (int j = 0; j < 4; j++) {
                float2 hf = __bfloat1622float2(*(__nv_bfloat162*)&hw[j]);
                float2 lf = __bfloat1622float2(*(__nv_bfloat162*)&lw[j]);
                s += (hf.x + lf.x) * vv[2 * j] + (hf.y + lf.y) * vv[2 * j + 1];
            }
        }
        s = warpSum(s);
        if (lane == 0) g_gv[b * MID + k] = s;
        return;
    }

    __nv_bfloat16* sAhi = sg;
    __nv_bfloat16* sAlo = sAhi + 64 * SB;
    __nv_bfloat16* sBhi = sAlo + 64 * SB;
    __nv_bfloat16* sBlo = sBhi + 64 * SB;
    uint32_t ub = s2u(sg);
    uint32_t uAhi = ub, uAlo = ub + 64 * SB * 2;
    uint32_t uBhi = uAlo + 64 * SB * 2, uBlo = uBhi + 64 * SB * 2;

    int aroff = (p == 0) ? 0 : 64;
    int broff = (p == 2) ? 128 : 0;
    int wi = wid & 1, wj = wid >> 1;

    float acc[2][4][4];
#pragma unroll
    for (int i = 0; i < 2; i++)
#pragma unroll
        for (int j = 0; j < 4; j++)
#pragma unroll
            for (int q = 0; q < 4; q++) acc[i][j][q] = 0.f;

    uint32_t aoff = ((uint32_t)(wi * 32 + (lane & 15)) * SB + (lane >> 4) * 8) * 2;
    uint32_t boff = ((uint32_t)(wj * 32 + ((lane >> 4) & 1) * 8 + (lane & 7)) * SB
                     + ((lane >> 3) & 1) * 8) * 2;

#pragma unroll 1
    for (int l = 0; l < 8; l++) {
        int nb = z * 256 + l * 32;
#pragma unroll
        for (int i = 0; i < 2; i++) {
            int unit = i * 128 + tid;      // 256 units = 64 rows x 4 uint4
            int row = unit >> 2, uc = unit & 3;
            size_t ga = ((size_t)b * 192 + aroff + row) * HWN + nb + uc * 8;
            size_t gb = ((size_t)b * 192 + broff + row) * HWN + nb + uc * 8;
            *(uint4*)(sAhi + row * SB + uc * 8) = *(const uint4*)(g_FGHkhi + ga);
            *(uint4*)(sAlo + row * SB + uc * 8) = *(const uint4*)(g_FGHklo + ga);
            *(uint4*)(sBhi + row * SB + uc * 8) = *(const uint4*)(g_FGHkhi + gb);
            *(uint4*)(sBlo + row * SB + uc * 8) = *(const uint4*)(g_FGHklo + gb);
        }
        __syncthreads();
#pragma unroll
        for (int ks = 0; ks < 2; ks++) {
            uint32_t kof = ks * 32;
            SPLIT3_STEP(acc, uAhi, uAlo, uBhi, uBlo, aoff, boff, kof);
        }
        __syncthreads();
    }

    float* dst = g_gram + ((size_t)p * BB + b) * MID * MID;
    int rq = lane >> 2, cq = (lane & 3) * 2;
#pragma unroll
    for (int mf = 0; mf < 2; mf++)
#pragma unroll
        for (int half = 0; half < 2; half++) {
            int i = wi * 32 + mf * 16 + rq + half * 8;
#pragma unroll
            for (int nf = 0; nf < 4; nf++) {
                int j = wj * 32 + nf * 8 + cq;
                atomicAdd(&dst[i * MID + j], acc[mf][nf][half * 2 + 0]);
                atomicAdd(&dst[i * MID + j + 1], acc[mf][nf][half * 2 + 1]);
            }
        }
}

// ---------------- kernel 4: Q = Wv @ M^T (unscaled) + fused s ---------------
// grid (BB, 64), 256 thr. Block (b, ro) computes Q rows [ro*4, ro*4+4) — one
// output per thread.
__global__ __launch_bounds__(256) void k_Qs(const float* __restrict__ Wv) {
    __shared__ float Mt[64 * 65];     // Mt[c*65 + k] = M[k][c]
    __shared__ float Ws[4 * 64];      // 4 Wv rows
    __shared__ float gvs[64], fvs[64], gvvs[64];
    int b = blockIdx.x, ro = blockIdx.y;
    int tid = threadIdx.x;

    const float* Mb = g_gram + ((size_t)2 * BB + b) * MID * MID;
#pragma unroll
    for (int i = 0; i < 16; i++) {
        int idx = i * 256 + tid;           // [0, 4096)
        int k = idx >> 6, c = idx & 63;
        Mt[c * 65 + k] = Mb[idx];
    }
    if (tid < 256) Ws[tid] = Wv[ro * 4 * MID + tid];

    if (ro == 0) {
        if (tid < 64) gvs[tid] = g_gv[b * MID + tid];
        __syncthreads();
#pragma unroll
        for (int it = 0; it < 2; it++) {
            int idx = it * 256 + tid;       // [0, 512)
            int row = idx >> 2, q = idx & 3;
            int pm = (row < 64) ? 0 : 1;
            int rl = row & 63;
            const float* A = g_gram + ((size_t)pm * BB + b) * MID * MID + rl * MID + q * 16;
            float ps = 0.f;
#pragma unroll
            for (int j = 0; j < 16; j++) ps += A[j] * gvs[q * 16 + j];
            ps += __shfl_down_sync(0xffffffffu, ps, 1);
            ps += __shfl_down_sync(0xffffffffu, ps, 2);
            if (q == 0) {
                if (row < 64) fvs[rl] = ps;
                else gvvs[rl] = ps;
            }
        }
        __syncthreads();
        if (tid < 32) {
            float ss = fvs[tid] * gvs[tid] + fvs[tid + 32] * gvs[tid + 32];
            float num = fvs[tid] * gvvs[tid] + fvs[tid + 32] * gvvs[tid + 32];
            ss = warpSum(ss);
            num = warpSum(num);
            if (tid == 0) g_s[b] = num / ss;
        }
    }
    __syncthreads();

    // one output per thread: row r = tid>>6 (Ws broadcast), col k = tid&63
    int r = tid >> 6;
    int k = tid & 63;
    float acc = 0.f;
#pragma unroll
    for (int c = 0; c < 64; c++)
        acc += Ws[r * 64 + c] * Mt[c * 65 + k];
    int orow = ro * 4 + r;
    size_t off = ((size_t)b * CC + orow) * MID + k;
    __nv_bfloat16 hi = __float2bfloat16(acc);
    float lo = acc - __bfloat162float(hi);
    g_Qhi[off] = hi;
    g_Qlo[off] = __float2bfloat16(lo);
}

// ---------------- kernel 5: out = (1/s) Q @ F + bv + x (dedup'd passes) -----
__global__ __launch_bounds__(256) void k_out_mma(const float* __restrict__ x,
                                                 const float* __restrict__ bv,
                                                 float* __restrict__ out) {
    __shared__ __align__(16) char sbuf[30720];
    __nv_bfloat16* sp = (__nv_bfloat16*)sbuf;
    __nv_bfloat16* sAhi = sp;
    __nv_bfloat16* sAlo = sAhi + 64 * SB;
    __nv_bfloat16* sBhi = sAlo + 64 * SB;
    __nv_bfloat16* sBlo = sBhi + 128 * SB;

    int tid = threadIdx.x;
    int wid = tid >> 5, lane = tid & 31;
    int b = blockIdx.z, mt = blockIdx.y;
    int nbase = blockIdx.x * 128;
    int wm = wid & 1, wn = wid >> 1;

    uint32_t ub = s2u(sbuf);
    uint32_t uAhi = ub, uAlo = ub + 64 * SB * 2;
    uint32_t uBhi = uAlo + 64 * SB * 2, uBlo = uBhi + 128 * SB * 2;

    float acc[2][4][4];
#pragma unroll
    for (int i = 0; i < 2; i++)
#pragma unroll
        for (int j = 0; j < 4; j++)
#pragma unroll
            for (int q = 0; q < 4; q++) acc[i][j][q] = 0.f;

    uint32_t aoff = ((uint32_t)(wm * 32 + (lane & 15)) * SB + (lane >> 4) * 8) * 2;
    uint32_t boff = ((uint32_t)(wn * 32 + ((lane >> 4) & 1) * 8 + (lane & 7)) * SB
                     + ((lane >> 3) & 1) * 8) * 2;

    int arow = tid >> 2, auc = tid & 3;
    const __nv_bfloat16* srcA0 = g_Qhi + ((size_t)b * CC + mt * 64 + arow) * MID + auc * 8;
    const __nv_bfloat16* srcA1 = g_Qlo + ((size_t)b * CC + mt * 64 + arow) * MID + auc * 8;
    const __nv_bfloat16* srcB0 = g_Fthi + ((size_t)b * HWN + nbase + arow) * MID + auc * 8;
    const __nv_bfloat16* srcB1 = g_Fthi + ((size_t)b * HWN + nbase + arow + 64) * MID + auc * 8;
    const __nv_bfloat16* srcB2 = g_Ftlo + ((size_t)b * HWN + nbase + arow) * MID + auc * 8;
    const __nv_bfloat16* srcB3 = g_Ftlo + ((size_t)b * HWN + nbase + arow + 64) * MID + auc * 8;

#pragma unroll 1
    for (int ki = 0; ki < MID / KC; ki++) {
        int kt = ki * KC;
        *(uint4*)(sAhi + arow * SB + auc * 8) = *(const uint4*)(srcA0 + kt);
        *(uint4*)(sAlo + arow * SB + auc * 8) = *(const uint4*)(srcA1 + kt);
        *(uint4*)(sBhi + arow * SB + auc * 8) = *(const uint4*)(srcB0 + kt);
        *(uint4*)(sBhi + (arow + 64) * SB + auc * 8) = *(const uint4*)(srcB1 + kt);
        *(uint4*)(sBlo + arow * SB + auc * 8) = *(const uint4*)(srcB2 + kt);
        *(uint4*)(sBlo + (arow + 64) * SB + auc * 8) = *(const uint4*)(srcB3 + kt);
        __syncthreads();
#pragma unroll
        for (int ks = 0; ks < 2; ks++) {
            uint32_t kof = ks * 32;
            SPLIT3_STEP(acc, uAhi, uAlo, uBhi, uBlo, aoff, boff, kof);
        }
        __syncthreads();
    }

    float inv_s = 1.f / g_s[b];
    int rq = lane >> 2;
    int cq = (lane & 3) * 2;
#pragma unroll
    for (int mf = 0; mf < 2; mf++) {
#pragma unroll
        for (int half = 0; half < 2; half++) {
            int orow = mt * 64 + wm * 32 + mf * 16 + rq + half * 8;
            float bias = bv[orow];
            size_t rowoff = ((size_t)b * CC + orow) * HWN + nbase + wn * 32;
#pragma unroll
            for (int nf = 0; nf < 4; nf++) {
                size_t off = rowoff + nf * 8 + cq;
                float2 xr = *(const float2*)(x + off);
                float2 v;
                v.x = acc[mf][nf][half * 2 + 0] * inv_s + bias + xr.x;
                v.y = acc[mf][nf][half * 2 + 1] * inv_s + bias + xr.y;
                *(float2*)(out + off) = v;
            }
        }
    }
}

// ---------------- launch ----------------
extern "C" void kernel_launch(void* const* d_in, const int* in_sizes, int n_in,
                              void* d_out, int out_size) {
    (void)in_sizes; (void)n_in; (void)out_size;
    const float* x   = (const float*)d_in[0];
    const float* Wf  = (const float*)d_in[1];
    const float* bf  = (const float*)d_in[2];
    const float* gaf = (const float*)d_in[3];
    const float* bef = (const float*)d_in[4];
    const float* mef = (const float*)d_in[5];
    const float* vaf = (const float*)d_in[6];
    const float* Wg  = (const float*)d_in[7];
    const float* bg  = (const float*)d_in[8];
    const float* gag = (const float*)d_in[9];
    const float* beg = (const float*)d_in[10];
    const float* meg = (const float*)d_in[11];
    const float* vag = (const float*)d_in[12];
    const float* Wh  = (const float*)d_in[13];
    const float* bh  = (const float*)d_in[14];
    const float* Wv  = (const float*)d_in[15];
    const float* bv  = (const float*)d_in[16];
    const float* v0  = (const float*)d_in[17];
    float* out = (float*)d_out;

    k_prepx<<<1024 + 192, 256>>>(x, Wf, bf, gaf, bef, mef, vaf,
                                 Wg, bg, gag, beg, meg, vag, Wh, bh);
    k_fgh_mma<<<dim3(HWN / 128, 3, BB), 256>>>();
    k_gramgv<<<dim3(BB, 4, 16), 128>>>(v0);
    k_Qs<<<dim3(BB, 64), 256>>>(Wv);
    k_out_mma<<<dim3(HWN / 128, 4, BB), 256>>>(x, bv, out);
}